// round 15
// baseline (speedup 1.0000x reference)
#include <cuda_runtime.h>
#include <math.h>

#define NROWS    32768
#define DD       256
#define KK       1024
#define BM       32
#define NTHREADS 512
#define NBLOCKS  (NROWS / BM)

#define SCAL_OFF 8388608         // 32768*256
#define IDX_OFF  8388612
#define FULL_OUT (8388608 + 4 + 32768)

// ---- global scratch (no allocs; zero-initialized at module load, reset by tail block) ----
__device__ float    g_avgp[KK];
__device__ float    g_sent;
__device__ float    g_diff;
__device__ unsigned g_ctr;
__device__ float    g_cbt[DD * KK];   // dim-major codebook: g_cbt[d*1024 + k]

// ---- smem layout in floats ----
#define DSM_OFF    0          // 32*1024 = 32768
#define XS_OFF     32768      // 32*256  = 8192
#define CST_OFF    40960      // 8*1032  = 8256  (codebook dim-major stage)
#define XSPB_OFF   49216      // 32*20   = 640   (x duplicated pairs)
#define CNS_OFF    49856      // 1024
#define XN_OFF     50880      // 32
#define REDW_OFF   50912      // 128
#define REDWI_OFF  51040      // 128 (ints)
#define DMIN_OFF   51168      // 32
#define IMIN_OFF   51200      // 32 (ints)
#define ZS_OFF     51232      // 32
#define IZ_OFF     51264      // 32
#define SENT_OFF   51296      // 32
#define FRED_OFF   51328      // 512
#define FLAG_OFF   51840      // 4
#define SMEM_FLOATS 51844     // 207376 bytes

#define CST_STRIDE  1032      // floats per dim row (1024 + pad), 4128B, 16B-aligned
#define XSPB_STRIDE 20        // floats per row (8 dup-pairs + pad), 80B, 16B-aligned

// packed dual FMA: two independent IEEE fma.rn.f32 lanes in one instruction.
#define FMA2(acc, a, b) \
    asm("fma.rn.f32x2 %0, %1, %2, %0;" : "+l"(acc) : "l"(a), "l"(b))

// dim-major transpose of the codebook (coalesced reads; writes hit L2 once)
__global__ void k_transpose(const float* __restrict__ cb) {
    int i = blockIdx.x * blockDim.x + threadIdx.x;   // 8192 threads
#pragma unroll
    for (int j = 0; j < 32; ++j) {
        int e = i + j * 8192;                        // e = k*256 + d
        int k = e >> 8, d = e & 255;
        g_cbt[d * KK + k] = cb[e];
    }
}

__global__ void __launch_bounds__(NTHREADS, 1)
k_main(const float* __restrict__ x, const float* __restrict__ cb,
       float* __restrict__ out, int write_extra)
{
    extern __shared__ float sm[];
    float* dsm  = sm + DSM_OFF;
    float* xs   = sm + XS_OFF;
    float* cst  = sm + CST_OFF;
    float* xspb = sm + XSPB_OFF;
    float* cns  = sm + CNS_OFF;
    float* xn   = sm + XN_OFF;
    float* redw = sm + REDW_OFF;
    int*   redwi= (int*)(sm + REDWI_OFF);
    float* dmin = sm + DMIN_OFF;
    int*   imin = (int*)(sm + IMIN_OFF);
    float* Zs   = sm + ZS_OFF;
    float* iZ   = sm + IZ_OFF;
    float* sent = sm + SENT_OFF;
    float* fred = sm + FRED_OFF;
    int*   flag = (int*)(sm + FLAG_OFF);

    const int tid = threadIdx.x;
    const int w   = tid >> 5;         // 0..15
    const int l   = tid & 31;
    const int gr0 = blockIdx.x * BM;

    float4* xs4 = (float4*)xs;
    const float4* cb4  = (const float4*)cb;
    const float4* cbt4 = (const float4*)g_cbt;
    const float4* x4   = (const float4*)(x + (size_t)gr0 * DD);

    // load x tile [32][256]
#pragma unroll
    for (int i = 0; i < 4; ++i) xs4[tid + i * 512] = x4[tid + i * 512];
    __syncthreads();

    // ---- ||c_k||^2 into cns: XLA x2-vectorized row-reduce (DO NOT TOUCH ops) ----
    // warp w handles codes w*64 .. w*64+63
    for (int t = 0; t < 64; ++t) {
        int k = w * 64 + t;
        const float2* c2 = (const float2*)(cb + (size_t)k * DD);
        float p = 0.f;
#pragma unroll
        for (int i = 0; i < 4; ++i) {
            float2 v = c2[l + 32 * i];
            p = fmaf(v.x, v.x, p);
            p = fmaf(v.y, v.y, p);
        }
#pragma unroll
        for (int off = 16; off; off >>= 1)
            p = __fadd_rn(p, __shfl_down_sync(0xffffffffu, p, off));
        if (l == 0) cns[k] = p;
    }

    // ---- per-row ||x||^2: same XLA realization (DO NOT TOUCH ops) ----
    for (int rr = 0; rr < 2; ++rr) {
        int r = rr * 16 + w;
        const float2* xr2 = (const float2*)(xs + r * DD);
        float p = 0.f;
#pragma unroll
        for (int i = 0; i < 4; ++i) {
            float2 v = xr2[l + 32 * i];
            p = fmaf(v.x, v.x, p);
            p = fmaf(v.y, v.y, p);
        }
#pragma unroll
        for (int off = 16; off; off >>= 1)
            p = __fadd_rn(p, __shfl_down_sync(0xffffffffu, p, off));
        if (l == 0) xn[r] = p;
    }

    // ---- distance GEMM: 8 rows x 8 codes per thread, packed f32x2 ----
    // Each f32x2 half is an independent serial fma.rn chain, k ascending 0..255
    // (bit-identical to the scalar FFMA chain of the passing R13 kernel).
    const int rg = w & 3, cg = w >> 2;
    const int r0 = rg * 8;
    const int c0 = cg * 128 + 4 * l;
    const int c1 = c0 + 512;

    unsigned long long acc[8][4];
#pragma unroll
    for (int i = 0; i < 8; ++i)
#pragma unroll
        for (int j = 0; j < 4; ++j) acc[i][j] = 0ull;

    for (int ds = 0; ds < DD; ds += 8) {
        __syncthreads();
        // stage cst[d][code] from dim-major global (coalesced)
#pragma unroll
        for (int i = 0; i < 4; ++i) {
            int idx = tid + i * 512;              // 0..2047 = 8 dims x 256 col-groups
            int d = idx >> 8, c4 = idx & 255;
            float4 v = cbt4[(size_t)(ds + d) * 256 + c4];
            *(float4*)(cst + d * CST_STRIDE + 4 * c4) = v;
        }
        // stage duplicated x pairs: xspb[row][kk] = (x, x)
        if (tid < 256) {
            int row = tid >> 3, kk = tid & 7;
            float v = xs[row * DD + ds + kk];
            *(float2*)(xspb + row * XSPB_STRIDE + kk * 2) = make_float2(v, v);
        }
        __syncthreads();

#pragma unroll
        for (int kk = 0; kk < 8; kk += 2) {
            ulonglong2 cva0 = *(const ulonglong2*)(cst + kk * CST_STRIDE + c0);
            ulonglong2 cva1 = *(const ulonglong2*)(cst + kk * CST_STRIDE + c1);
            ulonglong2 cvb0 = *(const ulonglong2*)(cst + (kk + 1) * CST_STRIDE + c0);
            ulonglong2 cvb1 = *(const ulonglong2*)(cst + (kk + 1) * CST_STRIDE + c1);
#pragma unroll
            for (int i = 0; i < 8; ++i) {
                ulonglong2 xp = *(const ulonglong2*)(xspb + (r0 + i) * XSPB_STRIDE + kk * 2);
                FMA2(acc[i][0], xp.x, cva0.x);
                FMA2(acc[i][1], xp.x, cva0.y);
                FMA2(acc[i][2], xp.x, cva1.x);
                FMA2(acc[i][3], xp.x, cva1.y);
                FMA2(acc[i][0], xp.y, cvb0.x);
                FMA2(acc[i][1], xp.y, cvb0.y);
                FMA2(acc[i][2], xp.y, cvb1.x);
                FMA2(acc[i][3], xp.y, cvb1.y);
            }
        }
    }

    // ---- epilogue: reference's exact fp32 chain (DO NOT TOUCH) + per-thread argmin ----
    float bd[8]; int bi[8];
#pragma unroll
    for (int i = 0; i < 8; ++i) { bd[i] = 3.4e38f; bi[i] = 0x7fffffff; }

#pragma unroll
    for (int i = 0; i < 8; ++i) {
        float xni = xn[r0 + i];
        float dq[4];
        // group A: codes c0..c0+3
#pragma unroll
        for (int u = 0; u < 4; ++u) {
            unsigned long long a = acc[i][u >> 1];
            float dot = (u & 1) ? __uint_as_float((unsigned)(a >> 32))
                                : __uint_as_float((unsigned)a);
            int k = c0 + u;
            float t  = __fadd_rn(xni, cns[k]);
            float d2 = __fadd_rn(t, __fmul_rn(-2.0f, dot));
            float d  = __fsqrt_rn(fmaxf(d2, 0.f));
            dq[u] = d;
            if (d < bd[i] || (d == bd[i] && k < bi[i])) { bd[i] = d; bi[i] = k; }
        }
        *(float4*)(dsm + (r0 + i) * KK + c0) = make_float4(dq[0], dq[1], dq[2], dq[3]);
        // group B: codes c1..c1+3
#pragma unroll
        for (int u = 0; u < 4; ++u) {
            unsigned long long a = acc[i][2 + (u >> 1)];
            float dot = (u & 1) ? __uint_as_float((unsigned)(a >> 32))
                                : __uint_as_float((unsigned)a);
            int k = c1 + u;
            float t  = __fadd_rn(xni, cns[k]);
            float d2 = __fadd_rn(t, __fmul_rn(-2.0f, dot));
            float d  = __fsqrt_rn(fmaxf(d2, 0.f));
            dq[u] = d;
            if (d < bd[i] || (d == bd[i] && k < bi[i])) { bd[i] = d; bi[i] = k; }
        }
        *(float4*)(dsm + (r0 + i) * KK + c1) = make_float4(dq[0], dq[1], dq[2], dq[3]);
    }

    // warp-level argmin reduce per row (index tie-break), then cross-warp
#pragma unroll
    for (int i = 0; i < 8; ++i) {
        float d = bd[i]; int ix = bi[i];
#pragma unroll
        for (int off = 16; off; off >>= 1) {
            float od = __shfl_down_sync(0xffffffffu, d, off);
            int   oi = __shfl_down_sync(0xffffffffu, ix, off);
            if (od < d || (od == d && oi < ix)) { d = od; ix = oi; }
        }
        if (l == 0) { redw[(r0 + i) * 4 + cg] = d; redwi[(r0 + i) * 4 + cg] = ix; }
    }
    __syncthreads();
    if (tid < 32) {
        float best = redw[tid * 4]; int besti = redwi[tid * 4];
#pragma unroll
        for (int c = 1; c < 4; ++c) {
            float v = redw[tid * 4 + c]; int vi = redwi[tid * 4 + c];
            if (v < best || (v == best && vi < besti)) { best = v; besti = vi; }
        }
        dmin[tid] = best; imin[tid] = besti;
    }
    __syncthreads();

    // ---- pass B1: per-row Z, W; overwrite dsm with e (16 threads/row, float4) ----
    {
        int r = tid >> 4, lq = tid & 15;
        float dm = dmin[r];
        float z = 0.f, wv = 0.f;
        float4* drow4 = (float4*)(dsm + r * KK);
#pragma unroll 4
        for (int i = 0; i < 16; ++i) {
            float4 d4v = drow4[lq + 16 * i];
            float a0 = (dm - d4v.x) * 100.0f, e0 = __expf(a0);
            float a1 = (dm - d4v.y) * 100.0f, e1 = __expf(a1);
            float a2 = (dm - d4v.z) * 100.0f, e2 = __expf(a2);
            float a3 = (dm - d4v.w) * 100.0f, e3 = __expf(a3);
            z += e0; wv = fmaf(e0, a0, wv);
            z += e1; wv = fmaf(e1, a1, wv);
            z += e2; wv = fmaf(e2, a2, wv);
            z += e3; wv = fmaf(e3, a3, wv);
            drow4[lq + 16 * i] = make_float4(e0, e1, e2, e3);
        }
#pragma unroll
        for (int off = 8; off; off >>= 1) {
            z  += __shfl_down_sync(0xffffffffu, z, off, 16);
            wv += __shfl_down_sync(0xffffffffu, wv, off, 16);
        }
        if (lq == 0) { Zs[r] = z; sent[r] = logf(z) - wv / z; }
    }
    __syncthreads();
    if (tid < 32) {
        iZ[tid] = 1.0f / Zs[tid];
        float sv = sent[tid];
        float dv = dmin[tid] * dmin[tid];
#pragma unroll
        for (int off = 16; off; off >>= 1) {
            sv += __shfl_down_sync(0xffffffffu, sv, off);
            dv += __shfl_down_sync(0xffffffffu, dv, off);
        }
        if (tid == 0) { atomicAdd(&g_sent, sv); atomicAdd(&g_diff, dv); }
    }
    __syncthreads();

    // ---- pass B2: avg_probs accumulation (2 atomics per column per block) ----
    {
        float4* dsm4 = (float4*)dsm;
        int c4 = tid & 255, half = tid >> 8;
        float s0 = 0.f, s1 = 0.f, s2 = 0.f, s3 = 0.f;
#pragma unroll 4
        for (int rr = 0; rr < 16; ++rr) {
            int r = half * 16 + rr;
            float4 e = dsm4[r * 256 + c4];
            float z = iZ[r];
            s0 = fmaf(e.x, z, s0); s1 = fmaf(e.y, z, s1);
            s2 = fmaf(e.z, z, s2); s3 = fmaf(e.w, z, s3);
        }
        atomicAdd(&g_avgp[c4 * 4 + 0], s0);
        atomicAdd(&g_avgp[c4 * 4 + 1], s1);
        atomicAdd(&g_avgp[c4 * 4 + 2], s2);
        atomicAdd(&g_avgp[c4 * 4 + 3], s3);
    }

    // ---- quantized STE output + indices ----
    {
        float4* out4 = (float4*)out;
#pragma unroll
        for (int i = 0; i < 4; ++i) {
            int f = tid + i * 512;
            int r = f >> 6, c4i = f & 63;
            int ki = imin[r];
            float4 q  = cb4[(size_t)ki * 64 + c4i];
            float4 xv = xs4[r * 64 + c4i];
            float4 o;
            o.x = xv.x + (q.x - xv.x);
            o.y = xv.y + (q.y - xv.y);
            o.z = xv.z + (q.z - xv.z);
            o.w = xv.w + (q.w - xv.w);
            out4[(size_t)(gr0 + r) * 64 + c4i] = o;
        }
        if (write_extra && tid < 32) out[IDX_OFF + gr0 + tid] = (float)imin[tid];
    }

    // ---- tail-block finalization (replaces k_final) + accumulator reset ----
    __syncthreads();
    if (tid == 0) {
        __threadfence();
        unsigned t = atomicAdd(&g_ctr, 1u);
        __threadfence();
        flag[0] = (t == (unsigned)(gridDim.x - 1)) ? 1 : 0;
    }
    __syncthreads();
    if (flag[0]) {
        float accv = 0.f;
        for (int k = tid; k < KK; k += 512) {
            float ap = g_avgp[k] * (1.0f / 32768.0f);
            accv += ap * logf(ap + 1e-5f);
        }
        fred[tid] = accv; __syncthreads();
        for (int s = 256; s; s >>= 1) { if (tid < s) fred[tid] += fred[tid + s]; __syncthreads(); }
        if (tid == 0 && write_extra) {
            float avg_ent = -fred[0];
            float samp = g_sent * (1.0f / 32768.0f);
            float S = 0.5f * g_diff * (1.0f / 8388608.0f);
            float entl = (samp - avg_ent) * 0.1f;
            float* outs = out + SCAL_OFF;
            outs[0] = S + 0.25f * S + entl;
            outs[1] = 0.25f * S;
            outs[2] = S;
            outs[3] = entl;
        }
        __syncthreads();
        for (int k = tid; k < KK; k += 512) g_avgp[k] = 0.f;
        if (tid == 0) { g_sent = 0.f; g_diff = 0.f; g_ctr = 0u; }
    }
}

extern "C" void kernel_launch(void* const* d_in, const int* in_sizes, int n_in,
                              void* d_out, int out_size) {
    const float* x;
    const float* cb;
    if (in_sizes[0] == NROWS * DD) { x = (const float*)d_in[0]; cb = (const float*)d_in[1]; }
    else                            { x = (const float*)d_in[1]; cb = (const float*)d_in[0]; }
    float* out = (float*)d_out;
    int write_extra = (out_size >= FULL_OUT) ? 1 : 0;

    size_t smem = SMEM_FLOATS * sizeof(float);
    cudaFuncSetAttribute(k_main, cudaFuncAttributeMaxDynamicSharedMemorySize, (int)smem);

    k_transpose<<<32, 256>>>(cb);
    k_main<<<NBLOCKS, NTHREADS, smem>>>(x, cb, out, write_extra);
}

// round 16
// speedup vs baseline: 1.0964x; 1.0964x over previous
#include <cuda_runtime.h>
#include <math.h>
#include <stdint.h>

#define NROWS    32768
#define DD       256
#define KK       1024
#define BM       32
#define NTHREADS 512
#define NBLOCKS  (NROWS / BM)

#define SCAL_OFF 8388608         // 32768*256
#define IDX_OFF  8388612
#define FULL_OUT (8388608 + 4 + 32768)

// ---- global scratch (no allocs; zeroed at load, reset by tail block) ----
__device__ float    g_avgp[KK];
__device__ float    g_sent;
__device__ float    g_diff;
__device__ unsigned g_ctr;
__device__ float    g_cnorm[KK];
__device__ float    g_cbt[DD * KK];   // dim-major codebook: g_cbt[d*1024 + k]

// ---- smem layout in floats ----
#define DSM_OFF    0          // 32*1024 = 32768
#define XS_OFF     32768      // 32*256  = 8192
#define CST_OFF    40960      // 2 buf * 4 dims * 1024 = 8192
#define XSPB_OFF   49152      // 2 buf * 32 rows * 20 = 1280
#define CNS_OFF    50432      // 1024
#define XN_OFF     51456      // 32
#define REDW_OFF   51488      // 128
#define REDWI_OFF  51616      // 128 (ints)
#define DMIN_OFF   51744      // 32
#define IMIN_OFF   51776      // 32 (ints)
#define ZS_OFF     51808      // 32
#define IZ_OFF     51840      // 32
#define SENT_OFF   51872      // 32
#define FRED_OFF   51904      // 512
#define FLAG_OFF   52416      // 4
#define SMEM_FLOATS 52420     // 209680 bytes

#define CST_BUF    4096       // floats per cst buffer (4 dims * 1024)
#define XSPB_BUF   640        // floats per xspb buffer (32 * 20)
#define XSPB_STRIDE 20

// packed dual FMA: two independent IEEE fma.rn.f32 lanes in one instruction.
#define FMA2(acc, a, b) \
    asm("fma.rn.f32x2 %0, %1, %2, %0;" : "+l"(acc) : "l"(a), "l"(b))

__device__ __forceinline__ void cp_async16(uint32_t dst, const void* src) {
    asm volatile("cp.async.cg.shared.global [%0], [%1], 16;" :: "r"(dst), "l"(src));
}
#define CP_COMMIT() asm volatile("cp.async.commit_group;" ::: "memory")
#define CP_WAIT0()  asm volatile("cp.async.wait_group 0;" ::: "memory")

// dim-major transpose of the codebook (coalesced reads)
__global__ void k_transpose(const float* __restrict__ cb) {
    int i = blockIdx.x * blockDim.x + threadIdx.x;   // 8192 threads
#pragma unroll
    for (int j = 0; j < 32; ++j) {
        int e = i + j * 8192;                        // e = k*256 + d
        int k = e >> 8, d = e & 255;
        g_cbt[d * KK + k] = cb[e];
    }
}

// ||c_k||^2 -- XLA GPU x2-vectorized row-reduce emulation (DO NOT TOUCH ops)
__global__ void k_cnorm(const float* __restrict__ cb) {
    int k = blockIdx.x, l = threadIdx.x;
    const float2* c2 = (const float2*)(cb + (size_t)k * DD);
    float p = 0.f;
#pragma unroll
    for (int i = 0; i < 4; ++i) {
        float2 v = c2[l + 32 * i];
        p = fmaf(v.x, v.x, p);
        p = fmaf(v.y, v.y, p);
    }
#pragma unroll
    for (int off = 16; off; off >>= 1)
        p = __fadd_rn(p, __shfl_down_sync(0xffffffffu, p, off));
    if (l == 0) g_cnorm[k] = p;
}

__global__ void __launch_bounds__(NTHREADS, 1)
k_main(const float* __restrict__ x, const float* __restrict__ cb,
       float* __restrict__ out, int write_extra)
{
    extern __shared__ float sm[];
    float* dsm  = sm + DSM_OFF;
    float* xs   = sm + XS_OFF;
    float* cst  = sm + CST_OFF;
    float* xspb = sm + XSPB_OFF;
    float* cns  = sm + CNS_OFF;
    float* xn   = sm + XN_OFF;
    float* redw = sm + REDW_OFF;
    int*   redwi= (int*)(sm + REDWI_OFF);
    float* dmin = sm + DMIN_OFF;
    int*   imin = (int*)(sm + IMIN_OFF);
    float* Zs   = sm + ZS_OFF;
    float* iZ   = sm + IZ_OFF;
    float* sent = sm + SENT_OFF;
    float* fred = sm + FRED_OFF;
    int*   flag = (int*)(sm + FLAG_OFF);

    const int tid = threadIdx.x;
    const int w   = tid >> 5;         // 0..15
    const int l   = tid & 31;
    const int gr0 = blockIdx.x * BM;

    float4* xs4 = (float4*)xs;
    const float4* cb4  = (const float4*)cb;
    const float4* cbt4 = (const float4*)g_cbt;
    const float4* x4   = (const float4*)(x + (size_t)gr0 * DD);

    // load x tile [32][256] + cns table
#pragma unroll
    for (int i = 0; i < 4; ++i) xs4[tid + i * 512] = x4[tid + i * 512];
    cns[tid]       = g_cnorm[tid];
    cns[tid + 512] = g_cnorm[tid + 512];
    __syncthreads();

    // ---- per-row ||x||^2: XLA x2-vectorized realization (DO NOT TOUCH ops) ----
    for (int rr = 0; rr < 2; ++rr) {
        int r = rr * 16 + w;
        const float2* xr2 = (const float2*)(xs + r * DD);
        float p = 0.f;
#pragma unroll
        for (int i = 0; i < 4; ++i) {
            float2 v = xr2[l + 32 * i];
            p = fmaf(v.x, v.x, p);
            p = fmaf(v.y, v.y, p);
        }
#pragma unroll
        for (int off = 16; off; off >>= 1)
            p = __fadd_rn(p, __shfl_down_sync(0xffffffffu, p, off));
        if (l == 0) xn[r] = p;
    }

    // ---- distance GEMM: 8 rows x 8 codes per thread, packed f32x2,
    //      cp.async double-buffered 4-dim stages ----
    const int rg = w & 3, cg = w >> 2;
    const int r0 = rg * 8;
    const int c0 = cg * 128 + 4 * l;
    const int c1 = c0 + 512;

    unsigned long long acc[8][4];
#pragma unroll
    for (int i = 0; i < 8; ++i)
#pragma unroll
        for (int j = 0; j < 4; ++j) acc[i][j] = 0ull;

    const int sd  = tid >> 8;          // staging: dim sub-index 0..1
    const int sc4 = tid & 255;         // staging: float4 group 0..255
    const int xrow = tid >> 2, xkk = tid & 3;   // xspb staging (tid<128)

    // prologue: stage 0 into buf 0
    {
        uint32_t dst = (uint32_t)__cvta_generic_to_shared(cst + (2 * 0 + sd) * KK + 4 * sc4);
        cp_async16(dst, cbt4 + (size_t)(0 + sd) * 256 + sc4);
        uint32_t dst2 = (uint32_t)__cvta_generic_to_shared(cst + (2 * 1 + sd) * KK + 4 * sc4);
        cp_async16(dst2, cbt4 + (size_t)(2 + sd) * 256 + sc4);
        CP_COMMIT();
        if (tid < 128) {
            float v = xs[xrow * DD + 0 + xkk];
            *(float2*)(xspb + xrow * XSPB_STRIDE + xkk * 2) = make_float2(v, v);
        }
        CP_WAIT0();
    }
    __syncthreads();

    for (int s = 0; s < 64; ++s) {
        const int buf = s & 1, nbuf = buf ^ 1;
        const float* cbase = cst + nbuf * 0 + buf * CST_BUF;   // cst + buf*4096
        const float* xbase = xspb + buf * XSPB_BUF;

        if (s + 1 < 64) {
            int ds2 = (s + 1) * 4;
            uint32_t d0 = (uint32_t)__cvta_generic_to_shared(cst + nbuf * CST_BUF + (2 * 0 + sd) * KK + 4 * sc4);
            cp_async16(d0, cbt4 + (size_t)(ds2 + sd) * 256 + sc4);
            uint32_t d1 = (uint32_t)__cvta_generic_to_shared(cst + nbuf * CST_BUF + (2 * 1 + sd) * KK + 4 * sc4);
            cp_async16(d1, cbt4 + (size_t)(ds2 + 2 + sd) * 256 + sc4);
            CP_COMMIT();
            if (tid < 128) {
                float v = xs[xrow * DD + ds2 + xkk];
                *(float2*)(xspb + nbuf * XSPB_BUF + xrow * XSPB_STRIDE + xkk * 2) = make_float2(v, v);
            }
        }

#pragma unroll
        for (int kk = 0; kk < 4; kk += 2) {
            ulonglong2 cva0 = *(const ulonglong2*)(cbase + kk * KK + c0);
            ulonglong2 cva1 = *(const ulonglong2*)(cbase + kk * KK + c1);
            ulonglong2 cvb0 = *(const ulonglong2*)(cbase + (kk + 1) * KK + c0);
            ulonglong2 cvb1 = *(const ulonglong2*)(cbase + (kk + 1) * KK + c1);
#pragma unroll
            for (int i = 0; i < 8; ++i) {
                ulonglong2 xp = *(const ulonglong2*)(xbase + (r0 + i) * XSPB_STRIDE + kk * 2);
                FMA2(acc[i][0], xp.x, cva0.x);
                FMA2(acc[i][1], xp.x, cva0.y);
                FMA2(acc[i][2], xp.x, cva1.x);
                FMA2(acc[i][3], xp.x, cva1.y);
                FMA2(acc[i][0], xp.y, cvb0.x);
                FMA2(acc[i][1], xp.y, cvb0.y);
                FMA2(acc[i][2], xp.y, cvb1.x);
                FMA2(acc[i][3], xp.y, cvb1.y);
            }
        }

        if (s + 1 < 64) CP_WAIT0();
        __syncthreads();
    }

    // ---- epilogue: reference's exact fp32 chain (DO NOT TOUCH) + per-thread argmin ----
    float bd[8]; int bi[8];
#pragma unroll
    for (int i = 0; i < 8; ++i) { bd[i] = 3.4e38f; bi[i] = 0x7fffffff; }

#pragma unroll
    for (int i = 0; i < 8; ++i) {
        float xni = xn[r0 + i];
        float dq[4];
#pragma unroll
        for (int u = 0; u < 4; ++u) {
            unsigned long long a = acc[i][u >> 1];
            float dot = (u & 1) ? __uint_as_float((unsigned)(a >> 32))
                                : __uint_as_float((unsigned)a);
            int k = c0 + u;
            float t  = __fadd_rn(xni, cns[k]);
            float d2 = __fadd_rn(t, __fmul_rn(-2.0f, dot));
            float d  = __fsqrt_rn(fmaxf(d2, 0.f));
            dq[u] = d;
            if (d < bd[i] || (d == bd[i] && k < bi[i])) { bd[i] = d; bi[i] = k; }
        }
        *(float4*)(dsm + (r0 + i) * KK + c0) = make_float4(dq[0], dq[1], dq[2], dq[3]);
#pragma unroll
        for (int u = 0; u < 4; ++u) {
            unsigned long long a = acc[i][2 + (u >> 1)];
            float dot = (u & 1) ? __uint_as_float((unsigned)(a >> 32))
                                : __uint_as_float((unsigned)a);
            int k = c1 + u;
            float t  = __fadd_rn(xni, cns[k]);
            float d2 = __fadd_rn(t, __fmul_rn(-2.0f, dot));
            float d  = __fsqrt_rn(fmaxf(d2, 0.f));
            dq[u] = d;
            if (d < bd[i] || (d == bd[i] && k < bi[i])) { bd[i] = d; bi[i] = k; }
        }
        *(float4*)(dsm + (r0 + i) * KK + c1) = make_float4(dq[0], dq[1], dq[2], dq[3]);
    }

    // warp-level argmin reduce per row (index tie-break), then cross-warp
#pragma unroll
    for (int i = 0; i < 8; ++i) {
        float d = bd[i]; int ix = bi[i];
#pragma unroll
        for (int off = 16; off; off >>= 1) {
            float od = __shfl_down_sync(0xffffffffu, d, off);
            int   oi = __shfl_down_sync(0xffffffffu, ix, off);
            if (od < d || (od == d && oi < ix)) { d = od; ix = oi; }
        }
        if (l == 0) { redw[(r0 + i) * 4 + cg] = d; redwi[(r0 + i) * 4 + cg] = ix; }
    }
    __syncthreads();
    if (tid < 32) {
        float best = redw[tid * 4]; int besti = redwi[tid * 4];
#pragma unroll
        for (int c = 1; c < 4; ++c) {
            float v = redw[tid * 4 + c]; int vi = redwi[tid * 4 + c];
            if (v < best || (v == best && vi < besti)) { best = v; besti = vi; }
        }
        dmin[tid] = best; imin[tid] = besti;
    }
    __syncthreads();

    // ---- pass B1: per-row Z, W; overwrite dsm with e (16 threads/row, float4) ----
    {
        int r = tid >> 4, lq = tid & 15;
        float dm = dmin[r];
        float z = 0.f, wv = 0.f;
        float4* drow4 = (float4*)(dsm + r * KK);
#pragma unroll 4
        for (int i = 0; i < 16; ++i) {
            float4 d4v = drow4[lq + 16 * i];
            float a0 = (dm - d4v.x) * 100.0f, e0 = __expf(a0);
            float a1 = (dm - d4v.y) * 100.0f, e1 = __expf(a1);
            float a2 = (dm - d4v.z) * 100.0f, e2 = __expf(a2);
            float a3 = (dm - d4v.w) * 100.0f, e3 = __expf(a3);
            z += e0; wv = fmaf(e0, a0, wv);
            z += e1; wv = fmaf(e1, a1, wv);
            z += e2; wv = fmaf(e2, a2, wv);
            z += e3; wv = fmaf(e3, a3, wv);
            drow4[lq + 16 * i] = make_float4(e0, e1, e2, e3);
        }
#pragma unroll
        for (int off = 8; off; off >>= 1) {
            z  += __shfl_down_sync(0xffffffffu, z, off, 16);
            wv += __shfl_down_sync(0xffffffffu, wv, off, 16);
        }
        if (lq == 0) { Zs[r] = z; sent[r] = logf(z) - wv / z; }
    }
    __syncthreads();
    if (tid < 32) {
        iZ[tid] = 1.0f / Zs[tid];
        float sv = sent[tid];
        float dv = dmin[tid] * dmin[tid];
#pragma unroll
        for (int off = 16; off; off >>= 1) {
            sv += __shfl_down_sync(0xffffffffu, sv, off);
            dv += __shfl_down_sync(0xffffffffu, dv, off);
        }
        if (tid == 0) { atomicAdd(&g_sent, sv); atomicAdd(&g_diff, dv); }
    }
    __syncthreads();

    // ---- pass B2: avg_probs accumulation (2 atomics per column per block) ----
    {
        float4* dsm4 = (float4*)dsm;
        int c4 = tid & 255, half = tid >> 8;
        float s0 = 0.f, s1 = 0.f, s2 = 0.f, s3 = 0.f;
#pragma unroll 4
        for (int rr = 0; rr < 16; ++rr) {
            int r = half * 16 + rr;
            float4 e = dsm4[r * 256 + c4];
            float z = iZ[r];
            s0 = fmaf(e.x, z, s0); s1 = fmaf(e.y, z, s1);
            s2 = fmaf(e.z, z, s2); s3 = fmaf(e.w, z, s3);
        }
        atomicAdd(&g_avgp[c4 * 4 + 0], s0);
        atomicAdd(&g_avgp[c4 * 4 + 1], s1);
        atomicAdd(&g_avgp[c4 * 4 + 2], s2);
        atomicAdd(&g_avgp[c4 * 4 + 3], s3);
    }

    // ---- quantized STE output + indices ----
    {
        float4* out4 = (float4*)out;
#pragma unroll
        for (int i = 0; i < 4; ++i) {
            int f = tid + i * 512;
            int r = f >> 6, c4i = f & 63;
            int ki = imin[r];
            float4 q  = cb4[(size_t)ki * 64 + c4i];
            float4 xv = xs4[r * 64 + c4i];
            float4 o;
            o.x = xv.x + (q.x - xv.x);
            o.y = xv.y + (q.y - xv.y);
            o.z = xv.z + (q.z - xv.z);
            o.w = xv.w + (q.w - xv.w);
            out4[(size_t)(gr0 + r) * 64 + c4i] = o;
        }
        if (write_extra && tid < 32) out[IDX_OFF + gr0 + tid] = (float)imin[tid];
    }

    // ---- tail-block finalization + accumulator reset ----
    __syncthreads();
    if (tid == 0) {
        __threadfence();
        unsigned t = atomicAdd(&g_ctr, 1u);
        __threadfence();
        flag[0] = (t == (unsigned)(gridDim.x - 1)) ? 1 : 0;
    }
    __syncthreads();
    if (flag[0]) {
        float accv = 0.f;
        for (int k = tid; k < KK; k += 512) {
            float ap = g_avgp[k] * (1.0f / 32768.0f);
            accv += ap * logf(ap + 1e-5f);
        }
        fred[tid] = accv; __syncthreads();
        for (int s = 256; s; s >>= 1) { if (tid < s) fred[tid] += fred[tid + s]; __syncthreads(); }
        if (tid == 0 && write_extra) {
            float avg_ent = -fred[0];
            float samp = g_sent * (1.0f / 32768.0f);
            float S = 0.5f * g_diff * (1.0f / 8388608.0f);
            float entl = (samp - avg_ent) * 0.1f;
            float* outs = out + SCAL_OFF;
            outs[0] = S + 0.25f * S + entl;
            outs[1] = 0.25f * S;
            outs[2] = S;
            outs[3] = entl;
        }
        __syncthreads();
        for (int k = tid; k < KK; k += 512) g_avgp[k] = 0.f;
        if (tid == 0) { g_sent = 0.f; g_diff = 0.f; g_ctr = 0u; }
    }
}

extern "C" void kernel_launch(void* const* d_in, const int* in_sizes, int n_in,
                              void* d_out, int out_size) {
    const float* x;
    const float* cb;
    if (in_sizes[0] == NROWS * DD) { x = (const float*)d_in[0]; cb = (const float*)d_in[1]; }
    else                            { x = (const float*)d_in[1]; cb = (const float*)d_in[0]; }
    float* out = (float*)d_out;
    int write_extra = (out_size >= FULL_OUT) ? 1 : 0;

    size_t smem = SMEM_FLOATS * sizeof(float);
    cudaFuncSetAttribute(k_main, cudaFuncAttributeMaxDynamicSharedMemorySize, (int)smem);

    k_transpose<<<32, 256>>>(cb);
    k_cnorm<<<KK, 32>>>(cb);
    k_main<<<NBLOCKS, NTHREADS, smem>>>(x, cb, out, write_extra);
}

// round 17
// speedup vs baseline: 1.2759x; 1.1637x over previous
#include <cuda_runtime.h>
#include <math.h>
#include <mma.h>
using namespace nvcuda;

#define NROWS    32768
#define DD       256
#define KK       1024
#define BM       32
#define NTHREADS 256
#define NBLOCKS  (NROWS / BM)

#define SCAL_OFF 8388608         // 32768*256
#define IDX_OFF  8388612
#define FULL_OUT (8388608 + 4 + 32768)

#define MAXCAND  8
#define MARGIN   2e-3f

// ---- global scratch ----
__device__ float g_avgp[KK];
__device__ float g_sent;
__device__ float g_diff;
__device__ float g_cnorm[KK];

// ---- smem layout in floats ----
#define DSM_OFF   0          // 32*1024 = 32768
#define XS_OFF    32768      // 8192
#define CNS_OFF   40960      // 1024
#define XN_OFF    41984      // 32
#define DMINS_OFF 42016      // 32 (screening dmin)
#define DMIN_OFF  42048      // 32
#define IMIN_OFF  42080      // 32 (ints)
#define CCNT_OFF  42112      // 32 (ints)
#define CAND_OFF  42144      // 256 (ints)
#define ZS_OFF    42400      // 32
#define IZ_OFF    42432      // 32
#define SENT_OFF  42464      // 32
#define SMEM_FLOATS 42496    // 169984 bytes

__global__ void k_zero() {
    int t = threadIdx.x;
    if (t < KK) g_avgp[t] = 0.f;
    if (t == 0) { g_sent = 0.f; g_diff = 0.f; }
}

// ||c_k||^2 -- XLA GPU x2-vectorized row-reduce emulation (DO NOT TOUCH ops)
__global__ void k_cnorm(const float* __restrict__ cb) {
    int k = blockIdx.x, l = threadIdx.x;
    const float2* c2 = (const float2*)(cb + (size_t)k * DD);
    float p = 0.f;
#pragma unroll
    for (int i = 0; i < 4; ++i) {
        float2 v = c2[l + 32 * i];
        p = fmaf(v.x, v.x, p);
        p = fmaf(v.y, v.y, p);
    }
#pragma unroll
    for (int off = 16; off; off >>= 1)
        p = __fadd_rn(p, __shfl_down_sync(0xffffffffu, p, off));
    if (l == 0) g_cnorm[k] = p;
}

__global__ void __launch_bounds__(NTHREADS, 1)
k_main(const float* __restrict__ x, const float* __restrict__ cb,
       float* __restrict__ out, int write_extra)
{
    extern __shared__ float sm[];
    float* dsm   = sm + DSM_OFF;
    float* xs    = sm + XS_OFF;
    float* cns   = sm + CNS_OFF;
    float* xn    = sm + XN_OFF;
    float* dmins = sm + DMINS_OFF;
    float* dmin  = sm + DMIN_OFF;
    int*   imin  = (int*)(sm + IMIN_OFF);
    int*   ccnt  = (int*)(sm + CCNT_OFF);
    int*   cand  = (int*)(sm + CAND_OFF);
    float* Zs    = sm + ZS_OFF;
    float* iZ    = sm + IZ_OFF;
    float* sent  = sm + SENT_OFF;

    const int tid = threadIdx.x;
    const int gr0 = blockIdx.x * BM;

    float4* xs4 = (float4*)xs;
    const float4* cb4 = (const float4*)cb;
    const float4* x4  = (const float4*)(x + (size_t)gr0 * DD);

    // load x tile [32][256] + cns table
#pragma unroll
    for (int i = 0; i < 8; ++i) xs4[tid + i * 256] = x4[tid + i * 256];
#pragma unroll
    for (int i = 0; i < 4; ++i) cns[tid + i * 256] = g_cnorm[tid + i * 256];
    __syncthreads();

    // ---- per-row ||x||^2: XLA x2-vectorized realization (DO NOT TOUCH ops) ----
    {
        int w = tid >> 5, lane = tid & 31;
        for (int rr = 0; rr < 4; ++rr) {
            int r = rr * 8 + w;
            const float2* xr2 = (const float2*)(xs + r * DD);
            float p = 0.f;
#pragma unroll
            for (int i = 0; i < 4; ++i) {
                float2 v = xr2[lane + 32 * i];
                p = fmaf(v.x, v.x, p);
                p = fmaf(v.y, v.y, p);
            }
#pragma unroll
            for (int off = 16; off; off >>= 1)
                p = __fadd_rn(p, __shfl_down_sync(0xffffffffu, p, off));
            if (lane == 0) xn[r] = p;
        }
    }

    // ---- TF32 wmma screening GEMM: dots -> dsm ----
    // warp w covers codes [w*128, w*128+128); A = xs [32x256] row-major;
    // B = cb [1024x256] row-major read as col-major (B[k][n] = cb[n][k]).
    {
        const int w = tid >> 5;
        const int n0w = w * 128;

        wmma::fragment<wmma::matrix_a, 16, 16, 8, wmma::precision::tf32, wmma::row_major> af[2];
        wmma::fragment<wmma::matrix_b, 16, 16, 8, wmma::precision::tf32, wmma::col_major> bf;
        wmma::fragment<wmma::accumulator, 16, 16, 8, float> cf[2][8];
#pragma unroll
        for (int mt = 0; mt < 2; ++mt)
#pragma unroll
            for (int nt = 0; nt < 8; ++nt) wmma::fill_fragment(cf[mt][nt], 0.f);

        for (int k0 = 0; k0 < DD; k0 += 8) {
#pragma unroll
            for (int mt = 0; mt < 2; ++mt) {
                wmma::load_matrix_sync(af[mt], xs + (mt * 16) * DD + k0, DD);
#pragma unroll
                for (int i = 0; i < af[mt].num_elements; ++i)
                    af[mt].x[i] = wmma::__float_to_tf32(af[mt].x[i]);
            }
#pragma unroll
            for (int nt = 0; nt < 8; ++nt) {
                wmma::load_matrix_sync(bf, cb + (size_t)(n0w + nt * 16) * DD + k0, DD);
#pragma unroll
                for (int i = 0; i < bf.num_elements; ++i)
                    bf.x[i] = wmma::__float_to_tf32(bf.x[i]);
                wmma::mma_sync(cf[0][nt], af[0], bf, cf[0][nt]);
                wmma::mma_sync(cf[1][nt], af[1], bf, cf[1][nt]);
            }
        }
#pragma unroll
        for (int mt = 0; mt < 2; ++mt)
#pragma unroll
            for (int nt = 0; nt < 8; ++nt)
                wmma::store_matrix_sync(dsm + (mt * 16) * KK + n0w + nt * 16,
                                        cf[mt][nt], KK, wmma::mem_row_major);
    }
    __syncthreads();

    // ---- transform dots -> screening d; per-row screening min ----
    {
        int r = tid >> 3, l = tid & 7;
        float xni = xn[r];
        float bd = 3.4e38f; int bi = 0x7fffffff;
        float* drow = dsm + r * KK;
#pragma unroll 4
        for (int i = 0; i < 128; ++i) {
            int k = l + (i << 3);
            float dot = drow[k];
            float t  = __fadd_rn(xni, cns[k]);
            float d2 = __fadd_rn(t, __fmul_rn(-2.0f, dot));
            float d  = __fsqrt_rn(fmaxf(d2, 0.f));
            drow[k] = d;
            if (d < bd || (d == bd && k < bi)) { bd = d; bi = k; }
        }
#pragma unroll
        for (int off = 4; off; off >>= 1) {
            float od = __shfl_down_sync(0xffffffffu, bd, off, 8);
            int   oi = __shfl_down_sync(0xffffffffu, bi, off, 8);
            if (od < bd || (od == bd && oi < bi)) { bd = od; bi = oi; }
        }
        if (l == 0) dmins[r] = bd;
    }
    if (tid < 32) ccnt[tid] = 0;
    __syncthreads();

    // ---- candidate scan within screening margin ----
    {
        int r = tid >> 3, l = tid & 7;
        float thr = dmins[r] + MARGIN;
        const float* drow = dsm + r * KK;
        for (int i = 0; i < 128; ++i) {
            int k = l + (i << 3);
            if (drow[k] <= thr) {
                int p = atomicAdd(&ccnt[r], 1);
                if (p < MAXCAND) cand[r * MAXCAND + p] = k;
            }
        }
    }
    __syncthreads();

    // ---- exact refinement: frozen bit-exact chain on candidates only ----
    // dot = serial ascending fmaf (cuBLAS per-output order); then
    // t = fl(xn+cn); d2 = fl(t - 2*dot); d = IEEE sqrt; (d,k)-lex argmin.
    {
        int r = tid >> 3, c = tid & 7;
        int n = ccnt[r] < MAXCAND ? ccnt[r] : MAXCAND;
        float bestd = 3.4e38f; int bestk = 0x7fffffff;
        const float* xrow = xs + r * DD;
        for (int ci = c; ci < n; ci += 8) {
            int k = cand[r * MAXCAND + ci];
            const float* crow = cb + (size_t)k * DD;
            float acc = 0.f;
#pragma unroll 8
            for (int kk = 0; kk < DD; ++kk)
                acc = fmaf(xrow[kk], crow[kk], acc);
            float t  = __fadd_rn(xn[r], cns[k]);
            float d2 = __fadd_rn(t, __fmul_rn(-2.0f, acc));
            float d  = __fsqrt_rn(fmaxf(d2, 0.f));
            if (d < bestd || (d == bestd && k < bestk)) { bestd = d; bestk = k; }
        }
#pragma unroll
        for (int off = 4; off; off >>= 1) {
            float od = __shfl_down_sync(0xffffffffu, bestd, off, 8);
            int   oi = __shfl_down_sync(0xffffffffu, bestk, off, 8);
            if (od < bestd || (od == bestd && oi < bestk)) { bestd = od; bestk = oi; }
        }
        if (c == 0) {
            dmin[r] = bestd; imin[r] = bestk;
            dsm[r * KK + bestk] = bestd;   // exact d at argmin -> a = 0 exactly
        }
    }
    __syncthreads();

    // ---- pass B1: per-row Z = sum e, W = sum e*a; overwrite dsm with e ----
    {
        int r = tid >> 3, l = tid & 7;
        float dm = dmin[r];
        float z = 0.f, w = 0.f;
        float* drow = dsm + r * KK;
#pragma unroll 4
        for (int i = 0; i < 128; ++i) {
            int k = l + (i << 3);
            float d = drow[k];
            float a = (dm - d) * 100.0f;     // 1/T, T = 0.01
            float e = __expf(a);
            z += e; w = fmaf(e, a, w);
            drow[k] = e;
        }
#pragma unroll
        for (int off = 4; off; off >>= 1) {
            z += __shfl_down_sync(0xffffffffu, z, off, 8);
            w += __shfl_down_sync(0xffffffffu, w, off, 8);
        }
        if (l == 0) { Zs[r] = z; sent[r] = logf(z) - w / z; }
    }
    __syncthreads();
    if (tid < 32) {
        iZ[tid] = 1.0f / Zs[tid];
        float sv = sent[tid];
        float dv = dmin[tid] * dmin[tid];   // == sum_d (x-q)^2 for this row
#pragma unroll
        for (int off = 16; off; off >>= 1) {
            sv += __shfl_down_sync(0xffffffffu, sv, off);
            dv += __shfl_down_sync(0xffffffffu, dv, off);
        }
        if (tid == 0) { atomicAdd(&g_sent, sv); atomicAdd(&g_diff, dv); }
    }
    __syncthreads();

    // ---- pass B2: avg_probs accumulation (one atomic per column per block) ----
    {
        float4* dsm4 = (float4*)dsm;
        float s0 = 0.f, s1 = 0.f, s2 = 0.f, s3 = 0.f;
#pragma unroll 4
        for (int r = 0; r < 32; ++r) {
            float4 e = dsm4[r * 256 + tid];
            float z = iZ[r];
            s0 = fmaf(e.x, z, s0); s1 = fmaf(e.y, z, s1);
            s2 = fmaf(e.z, z, s2); s3 = fmaf(e.w, z, s3);
        }
        atomicAdd(&g_avgp[tid * 4 + 0], s0);
        atomicAdd(&g_avgp[tid * 4 + 1], s1);
        atomicAdd(&g_avgp[tid * 4 + 2], s2);
        atomicAdd(&g_avgp[tid * 4 + 3], s3);
    }

    // ---- quantized STE output + indices ----
    {
        float4* out4 = (float4*)out;
#pragma unroll
        for (int i = 0; i < 8; ++i) {
            int f = tid + i * 256;
            int r = f >> 6, c4i = f & 63;
            int ki = imin[r];
            float4 q  = cb4[(size_t)ki * 64 + c4i];
            float4 xv = xs4[r * 64 + c4i];
            float4 o;
            o.x = xv.x + (q.x - xv.x);
            o.y = xv.y + (q.y - xv.y);
            o.z = xv.z + (q.z - xv.z);
            o.w = xv.w + (q.w - xv.w);
            out4[(size_t)(gr0 + r) * 64 + c4i] = o;
        }
        if (write_extra && tid < 32) out[IDX_OFF + gr0 + tid] = (float)imin[tid];
    }
}

__global__ void k_final(float* __restrict__ outs) {
    __shared__ float red[256];
    int t = threadIdx.x;
    float acc = 0.f;
    for (int k = t; k < KK; k += 256) {
        float ap = g_avgp[k] * (1.0f / 32768.0f);
        acc += ap * logf(ap + 1e-5f);
    }
    red[t] = acc; __syncthreads();
    for (int s = 128; s; s >>= 1) { if (t < s) red[t] += red[t + s]; __syncthreads(); }
    if (t == 0) {
        float avg_ent = -red[0];
        float samp = g_sent * (1.0f / 32768.0f);
        float S = 0.5f * g_diff * (1.0f / 8388608.0f);  // codebook_loss
        float entl = (samp - avg_ent) * 0.1f;
        outs[0] = S + 0.25f * S + entl;  // vq_loss
        outs[1] = 0.25f * S;             // commit_loss
        outs[2] = S;                     // codebook_loss
        outs[3] = entl;                  // entropy_loss
    }
}

extern "C" void kernel_launch(void* const* d_in, const int* in_sizes, int n_in,
                              void* d_out, int out_size) {
    const float* x;
    const float* cb;
    if (in_sizes[0] == NROWS * DD) { x = (const float*)d_in[0]; cb = (const float*)d_in[1]; }
    else                            { x = (const float*)d_in[1]; cb = (const float*)d_in[0]; }
    float* out = (float*)d_out;
    int write_extra = (out_size >= FULL_OUT) ? 1 : 0;

    size_t smem = SMEM_FLOATS * sizeof(float);
    cudaFuncSetAttribute(k_main, cudaFuncAttributeMaxDynamicSharedMemorySize, (int)smem);

    k_zero<<<1, 1024>>>();
    k_cnorm<<<KK, 32>>>(cb);
    k_main<<<NBLOCKS, NTHREADS, smem>>>(x, cb, out, write_extra);
    if (write_extra) k_final<<<1, 256>>>(out + SCAL_OFF);
}